// round 13
// baseline (speedup 1.0000x reference)
#include <cuda_runtime.h>
#include <cuda_bf16.h>
#include <cuda_fp16.h>

// GINConv forward: out = segment_sum(X[ci]) @ W  ==  segment_sum((X@W)[ci])
// Kernel 1: Y = X @ W, fp16 out. 128 thr/block, 4 rows x 8 cols per thread,
//           conflict-free Xs (stride 65, rows ty + j*16), ST.128 epilogue.
//           (R12 design with the W-staging bound fixed: 1024 float4, not 256.)
// Kernel 2: out = segment_sum(Y[ci]) — proven R11 schedule (half-warp/node,
//           4 broadcast ci loads + 4 uint2 gathers + HADD2), 64-thr blocks.

#define D_FEAT 64
#define N_NODES_MAX 100000

// Scratch for Y in fp16 (12.8 MB). __device__ global: allowed (no alloc).
__device__ __align__(16) __half g_Yh[(size_t)N_NODES_MAX * D_FEAT];

// ---- packed f32x2 helpers (sm_103a) ----
__device__ __forceinline__ unsigned long long pk2(float lo, float hi) {
    unsigned long long r;
    asm("mov.b64 %0, {%1, %2};" : "=l"(r) : "f"(lo), "f"(hi));
    return r;
}
__device__ __forceinline__ void unpk2(unsigned long long v, float& lo, float& hi) {
    asm("mov.b64 {%0, %1}, %2;" : "=f"(lo), "=f"(hi) : "l"(v));
}
__device__ __forceinline__ void fma2(unsigned long long& d,
                                     unsigned long long a,
                                     unsigned long long b) {
    asm("fma.rn.f32x2 %0, %1, %2, %0;" : "+l"(d) : "l"(a), "l"(b));
}

// Packed fp16 accumulate: a += v  (two add.f16x2 per uint2 = 4 halves)
__device__ __forceinline__ void hacc(uint2& a, const uint2 v) {
    __half2& alo = *reinterpret_cast<__half2*>(&a.x);
    __half2& ahi = *reinterpret_cast<__half2*>(&a.y);
    alo = __hadd2(alo, *reinterpret_cast<const __half2*>(&v.x));
    ahi = __hadd2(ahi, *reinterpret_cast<const __half2*>(&v.y));
}

// Convert uint2 (4 halves) to float4
__device__ __forceinline__ float4 h4f(const uint2 u) {
    const float2 f0 = __half22float2(*reinterpret_cast<const __half2*>(&u.x));
    const float2 f1 = __half22float2(*reinterpret_cast<const __half2*>(&u.y));
    return make_float4(f0.x, f0.y, f1.x, f1.y);
}

// Pack a u64 fp32 pair into one half2 word
__device__ __forceinline__ unsigned h2pack(unsigned long long p) {
    float a, b;
    unpk2(p, a, b);
    const __half2 h = __float22half2_rn(make_float2(a, b));
    return *reinterpret_cast<const unsigned*>(&h);
}

#define XS_STRIDE 65   // odd stride -> 16 ty-groups hit 16 distinct banks

// ================= Kernel 1: Y = X @ W (fp16 out) =================
// 64-row tile per block, 128 threads as 16(ty) x 8(tx).
// Thread (ty,tx) computes rows {ty + 16j} x cols [8tx, 8tx+8).
__global__ __launch_bounds__(128) void gemm_xw_kernel(
    const float* __restrict__ X,
    const float* __restrict__ W,
    uint4* __restrict__ Yh4,      // [n_rows * 8] uint4 (8 halves each)
    int n_rows)
{
    __shared__ __align__(16) float Xs[D_FEAT * XS_STRIDE];       // 16.6 KB
    __shared__ __align__(16) unsigned long long Wp[D_FEAT * 32]; // 16 KB

    const int tid = threadIdx.x;
    const int ty = tid >> 3;       // 0..15
    const int tx = tid & 7;        // 0..7
    const int base = blockIdx.x * 64;

    // Stage W packed as (col2p, col2p+1) pairs.
    // W = 64x64 floats = 1024 float4 total (16 float4 per 64-float row).
    #pragma unroll
    for (int i = tid; i < 1024; i += 128) {
        const float4 w4 = reinterpret_cast<const float4*>(W)[i];
        const int kk = i >> 4;             // W row (k index), 0..63
        const int qq = i & 15;             // float4 within row, 0..15
        Wp[kk * 32 + 2 * qq + 0] = pk2(w4.x, w4.y);
        Wp[kk * 32 + 2 * qq + 1] = pk2(w4.z, w4.w);
    }
    // Stage X tile: 1024 float4 over 128 threads (coalesced)
    #pragma unroll
    for (int i = tid; i < 1024; i += 128) {
        const int r = i >> 4, q = i & 15;
        float4 v = make_float4(0.f, 0.f, 0.f, 0.f);
        if (base + r < n_rows)
            v = reinterpret_cast<const float4*>(X)[(size_t)(base + r) * 16 + q];
        float* xr = Xs + r * XS_STRIDE + q * 4;
        xr[0] = v.x; xr[1] = v.y; xr[2] = v.z; xr[3] = v.w;
    }
    __syncthreads();

    unsigned long long acc[4][4] = {};   // 4 rows x 4 col-pairs (8 cols)

    #pragma unroll 4
    for (int k = 0; k < D_FEAT; ++k) {
        const longlong2* wr = reinterpret_cast<const longlong2*>(Wp + k * 32);
        const longlong2 wa = wr[tx * 2 + 0];   // cols 8tx..8tx+3
        const longlong2 wb = wr[tx * 2 + 1];   // cols 8tx+4..8tx+7
        #pragma unroll
        for (int j = 0; j < 4; ++j) {
            const float x = Xs[(ty + j * 16) * XS_STRIDE + k]; // conflict-free
            const unsigned long long xx = pk2(x, x);
            fma2(acc[j][0], xx, (unsigned long long)wa.x);
            fma2(acc[j][1], xx, (unsigned long long)wa.y);
            fma2(acc[j][2], xx, (unsigned long long)wb.x);
            fma2(acc[j][3], xx, (unsigned long long)wb.y);
        }
    }

    #pragma unroll
    for (int j = 0; j < 4; ++j) {
        const int row = base + ty + j * 16;
        if (row < n_rows) {
            uint4 u;
            u.x = h2pack(acc[j][0]);
            u.y = h2pack(acc[j][1]);
            u.z = h2pack(acc[j][2]);
            u.w = h2pack(acc[j][3]);
            Yh4[(size_t)row * 8 + tx] = u;   // one ST.128 per row
        }
    }
}

// ============ Kernel 2: out = segment_sum(Y[ci]) ============
// Half-warp (16 lanes) per node; lane fl owns 4 halves (uint2) of the row.
// 4 broadcast ci loads + 4 independent gathers per trip; HADD2 accumulation
// into 4 independent fp16 accumulator sets. 64-thread blocks for the finest
// retirement granularity under degree variance.
__global__ __launch_bounds__(64, 24) void gather_sum_kernel(
    const uint2* __restrict__ Yh2,
    const int* __restrict__ rp,
    const int* __restrict__ ci,
    float4* __restrict__ out4,
    int n_nodes)
{
    const int tid  = threadIdx.x;
    const int half = tid >> 4;     // half-warp id within block: 0..3
    const int fl   = tid & 15;     // uint2 index within the 128B row
    const int node = blockIdx.x * 4 + half;
    if (node >= n_nodes) return;

    const int start = __ldg(&rp[node]);
    const int end   = __ldg(&rp[node + 1]);

    uint2 a0 = make_uint2(0u, 0u);   // half2 zeros
    uint2 a1 = a0, a2 = a0, a3 = a0;

    int e = start;
    for (; e + 4 <= end; e += 4) {
        const int c0 = __ldg(&ci[e + 0]);
        const int c1 = __ldg(&ci[e + 1]);
        const int c2 = __ldg(&ci[e + 2]);
        const int c3 = __ldg(&ci[e + 3]);
        const uint2 v0 = __ldg(&Yh2[(size_t)c0 * 16 + fl]);
        const uint2 v1 = __ldg(&Yh2[(size_t)c1 * 16 + fl]);
        const uint2 v2 = __ldg(&Yh2[(size_t)c2 * 16 + fl]);
        const uint2 v3 = __ldg(&Yh2[(size_t)c3 * 16 + fl]);
        hacc(a0, v0);
        hacc(a1, v1);
        hacc(a2, v2);
        hacc(a3, v3);
    }
    for (; e < end; ++e) {
        const int c = __ldg(&ci[e]);
        const uint2 v = __ldg(&Yh2[(size_t)c * 16 + fl]);
        hacc(a0, v);
    }

    // Final combine in fp32 (one conversion per accumulator set)
    const float4 f0 = h4f(a0);
    const float4 f1 = h4f(a1);
    const float4 f2 = h4f(a2);
    const float4 f3 = h4f(a3);

    float4 r;
    r.x = (f0.x + f1.x) + (f2.x + f3.x);
    r.y = (f0.y + f1.y) + (f2.y + f3.y);
    r.z = (f0.z + f1.z) + (f2.z + f3.z);
    r.w = (f0.w + f1.w) + (f2.w + f3.w);

    out4[(size_t)node * 16 + fl] = r;   // warp = 2 consecutive rows: coalesced
}

extern "C" void kernel_launch(void* const* d_in, const int* in_sizes, int n_in,
                              void* d_out, int out_size) {
    const float* X  = (const float*)d_in[0];   // [100000, 64]
    const float* W  = (const float*)d_in[1];   // [64, 64]
    const int*   rp = (const int*)d_in[2];     // [100001]
    const int*   ci = (const int*)d_in[3];     // [1600000]
    float* out = (float*)d_out;                // [100000, 64]

    const int n_nodes = in_sizes[2] - 1;       // 100000

    __half* Yptr = nullptr;
    cudaGetSymbolAddress((void**)&Yptr, g_Yh);

    const int blocks1 = (n_nodes + 63) / 64;
    gemm_xw_kernel<<<blocks1, 128>>>(X, W, reinterpret_cast<uint4*>(Yptr),
                                     n_nodes);

    const int blocks2 = (n_nodes + 3) / 4;
    gather_sum_kernel<<<blocks2, 64>>>(
        reinterpret_cast<const uint2*>(Yptr), rp, ci,
        reinterpret_cast<float4*>(out), n_nodes);
}

// round 14
// speedup vs baseline: 1.1698x; 1.1698x over previous
#include <cuda_runtime.h>
#include <cuda_bf16.h>
#include <cuda_fp16.h>

// GINConv forward: out = segment_sum(X[ci]) @ W  ==  segment_sum((X@W)[ci])
// Kernel 1: Y = X @ W, fp16 out — exact R11 version (proven 18.4us).
// Kernel 2: out = segment_sum(Y[ci]) — R11 half-warp schedule with the main
//           loop deepened to 8 edges/trip (16 outstanding LDGs/warp) at
//           ~constant occupancy thanks to fp16 register economics.

#define D_FEAT 64
#define N_NODES_MAX 100000

// Scratch for Y in fp16 (12.8 MB). __device__ global: allowed (no alloc).
__device__ __align__(16) __half g_Yh[(size_t)N_NODES_MAX * D_FEAT];

// ---- packed f32x2 helpers (sm_103a) ----
__device__ __forceinline__ unsigned long long pk2(float lo, float hi) {
    unsigned long long r;
    asm("mov.b64 %0, {%1, %2};" : "=l"(r) : "f"(lo), "f"(hi));
    return r;
}
__device__ __forceinline__ void unpk2(unsigned long long v, float& lo, float& hi) {
    asm("mov.b64 {%0, %1}, %2;" : "=f"(lo), "=f"(hi) : "l"(v));
}
__device__ __forceinline__ void fma2(unsigned long long& d,
                                     unsigned long long a,
                                     unsigned long long b) {
    asm("fma.rn.f32x2 %0, %1, %2, %0;" : "+l"(d) : "l"(a), "l"(b));
}

// Packed fp16 accumulate: a += v  (two add.f16x2 per uint2 = 4 halves)
__device__ __forceinline__ void hacc(uint2& a, const uint2 v) {
    __half2& alo = *reinterpret_cast<__half2*>(&a.x);
    __half2& ahi = *reinterpret_cast<__half2*>(&a.y);
    alo = __hadd2(alo, *reinterpret_cast<const __half2*>(&v.x));
    ahi = __hadd2(ahi, *reinterpret_cast<const __half2*>(&v.y));
}

// Convert uint2 (4 halves) to float4
__device__ __forceinline__ float4 h4f(const uint2 u) {
    const float2 f0 = __half22float2(*reinterpret_cast<const __half2*>(&u.x));
    const float2 f1 = __half22float2(*reinterpret_cast<const __half2*>(&u.y));
    return make_float4(f0.x, f0.y, f1.x, f1.y);
}

// ================= Kernel 1: Y = X @ W (fp16 out) — R11 exact =============
// 64-row tile per block, 256 threads as 16x16, each thread a 4x4 micro-tile.
__global__ __launch_bounds__(256) void gemm_xw_kernel(
    const float* __restrict__ X,
    const float* __restrict__ W,
    uint2* __restrict__ Yh2,      // [n_rows * 16] uint2 (4 halves each)
    int n_rows)
{
    __shared__ __align__(16) float Xs[D_FEAT][68];               // 17.4 KB
    __shared__ __align__(16) unsigned long long Wp[D_FEAT * 32]; // 16 KB

    const int tid = threadIdx.x;
    const int ty = tid >> 4;
    const int tx = tid & 15;
    const int base = blockIdx.x * 64;

    #pragma unroll
    for (int i = tid; i < 1024; i += 256) {
        const float4 w4 = reinterpret_cast<const float4*>(W)[i];
        const int k = i >> 4, p = i & 15;
        Wp[k * 32 + 2 * p + 0] = pk2(w4.x, w4.y);
        Wp[k * 32 + 2 * p + 1] = pk2(w4.z, w4.w);
    }
    #pragma unroll
    for (int i = tid; i < 1024; i += 256) {
        const int r = i >> 4, q = i & 15;
        float4 v = make_float4(0.f, 0.f, 0.f, 0.f);
        if (base + r < n_rows)
            v = reinterpret_cast<const float4*>(X)[(size_t)(base + r) * 16 + q];
        *reinterpret_cast<float4*>(&Xs[r][q * 4]) = v;
    }
    __syncthreads();

    unsigned long long acc[4][2] = {};

    #pragma unroll 4
    for (int k = 0; k < D_FEAT; ++k) {
        const longlong2 w2 =
            reinterpret_cast<const longlong2*>(Wp + k * 32)[tx];
        #pragma unroll
        for (int j = 0; j < 4; ++j) {
            const float x = Xs[ty * 4 + j][k];
            const unsigned long long xx = pk2(x, x);
            fma2(acc[j][0], xx, (unsigned long long)w2.x);
            fma2(acc[j][1], xx, (unsigned long long)w2.y);
        }
    }

    #pragma unroll
    for (int j = 0; j < 4; ++j) {
        const int row = base + ty * 4 + j;
        if (row < n_rows) {
            float a, b, c, d;
            unpk2(acc[j][0], a, b);
            unpk2(acc[j][1], c, d);
            const __half2 h0 = __float22half2_rn(make_float2(a, b));
            const __half2 h1 = __float22half2_rn(make_float2(c, d));
            uint2 u;
            u.x = *reinterpret_cast<const unsigned*>(&h0);
            u.y = *reinterpret_cast<const unsigned*>(&h1);
            Yh2[(size_t)row * 16 + tx] = u;
        }
    }
}

// ============ Kernel 2: out = segment_sum(Y[ci]) ============
// Half-warp (16 lanes) per node; lane fl owns 4 halves (uint2) of the row.
// Main loop: 8 broadcast ci loads + 8 independent uint2 gathers per trip
// (16 outstanding LDGs/warp), HADD2 into 4 fp16 accumulator sets.
__global__ __launch_bounds__(128, 8) void gather_sum_kernel(
    const uint2* __restrict__ Yh2,
    const int* __restrict__ rp,
    const int* __restrict__ ci,
    float4* __restrict__ out4,
    int n_nodes)
{
    const int tid  = threadIdx.x;
    const int half = tid >> 4;     // half-warp id within block: 0..7
    const int fl   = tid & 15;     // uint2 index within the 128B row
    const int node = blockIdx.x * 8 + half;
    if (node >= n_nodes) return;

    const int start = __ldg(&rp[node]);
    const int end   = __ldg(&rp[node + 1]);

    uint2 a0 = make_uint2(0u, 0u);   // half2 zeros
    uint2 a1 = a0, a2 = a0, a3 = a0;

    int e = start;

    // Main: 8 edges per trip -> 8 independent gathers in flight
    for (; e + 8 <= end; e += 8) {
        const int c0 = __ldg(&ci[e + 0]);
        const int c1 = __ldg(&ci[e + 1]);
        const int c2 = __ldg(&ci[e + 2]);
        const int c3 = __ldg(&ci[e + 3]);
        const int c4 = __ldg(&ci[e + 4]);
        const int c5 = __ldg(&ci[e + 5]);
        const int c6 = __ldg(&ci[e + 6]);
        const int c7 = __ldg(&ci[e + 7]);
        const uint2 v0 = __ldg(&Yh2[(size_t)c0 * 16 + fl]);
        const uint2 v1 = __ldg(&Yh2[(size_t)c1 * 16 + fl]);
        const uint2 v2 = __ldg(&Yh2[(size_t)c2 * 16 + fl]);
        const uint2 v3 = __ldg(&Yh2[(size_t)c3 * 16 + fl]);
        const uint2 v4 = __ldg(&Yh2[(size_t)c4 * 16 + fl]);
        const uint2 v5 = __ldg(&Yh2[(size_t)c5 * 16 + fl]);
        const uint2 v6 = __ldg(&Yh2[(size_t)c6 * 16 + fl]);
        const uint2 v7 = __ldg(&Yh2[(size_t)c7 * 16 + fl]);
        hacc(a0, v0); hacc(a1, v1); hacc(a2, v2); hacc(a3, v3);
        hacc(a0, v4); hacc(a1, v5); hacc(a2, v6); hacc(a3, v7);
    }

    // 4-edge chunk
    if (e + 4 <= end) {
        const int c0 = __ldg(&ci[e + 0]);
        const int c1 = __ldg(&ci[e + 1]);
        const int c2 = __ldg(&ci[e + 2]);
        const int c3 = __ldg(&ci[e + 3]);
        const uint2 v0 = __ldg(&Yh2[(size_t)c0 * 16 + fl]);
        const uint2 v1 = __ldg(&Yh2[(size_t)c1 * 16 + fl]);
        const uint2 v2 = __ldg(&Yh2[(size_t)c2 * 16 + fl]);
        const uint2 v3 = __ldg(&Yh2[(size_t)c3 * 16 + fl]);
        hacc(a0, v0); hacc(a1, v1); hacc(a2, v2); hacc(a3, v3);
        e += 4;
    }

    // Scalar tail
    for (; e < end; ++e) {
        const int c = __ldg(&ci[e]);
        const uint2 v = __ldg(&Yh2[(size_t)c * 16 + fl]);
        hacc(a0, v);
    }

    // Final combine in fp32 (one conversion per accumulator set)
    const float4 f0 = h4f(a0);
    const float4 f1 = h4f(a1);
    const float4 f2 = h4f(a2);
    const float4 f3 = h4f(a3);

    float4 r;
    r.x = (f0.x + f1.x) + (f2.x + f3.x);
    r.y = (f0.y + f1.y) + (f2.y + f3.y);
    r.z = (f0.z + f1.z) + (f2.z + f3.z);
    r.w = (f0.w + f1.w) + (f2.w + f3.w);

    out4[(size_t)node * 16 + fl] = r;   // warp = 2 consecutive rows: coalesced
}

extern "C" void kernel_launch(void* const* d_in, const int* in_sizes, int n_in,
                              void* d_out, int out_size) {
    const float* X  = (const float*)d_in[0];   // [100000, 64]
    const float* W  = (const float*)d_in[1];   // [64, 64]
    const int*   rp = (const int*)d_in[2];     // [100001]
    const int*   ci = (const int*)d_in[3];     // [1600000]
    float* out = (float*)d_out;                // [100000, 64]

    const int n_nodes = in_sizes[2] - 1;       // 100000

    __half* Yptr = nullptr;
    cudaGetSymbolAddress((void**)&Yptr, g_Yh);
    uint2* Yh2 = reinterpret_cast<uint2*>(Yptr);

    const int blocks1 = (n_nodes + 63) / 64;
    gemm_xw_kernel<<<blocks1, 256>>>(X, W, Yh2, n_nodes);

    const int blocks2 = (n_nodes + 7) / 8;
    gather_sum_kernel<<<blocks2, 128>>>(
        Yh2, rp, ci, reinterpret_cast<float4*>(out), n_nodes);
}